// round 3
// baseline (speedup 1.0000x reference)
#include <cuda_runtime.h>
#include <cfloat>
#include <climits>
#include <math.h>

// Problem constants
#define Bc 4
#define Nc 500
#define Cc 80
#define Tc 28
#define TTc 784
#define Mc 16
#define Hc 800
#define Wc 800
#define EPSc 1e-8f
#define CANDK 10

// Scratch (device globals; no allocation allowed)
__device__ float g_gm[Bc * Mc * TTc];     // cropped+binarized gt masks
__device__ float g_gmsum[Bc * Mc];        // per gt mask sums
__device__ float g_inter[Bc * Nc * Mc];   // [b][n][m] sum_t ms*gm
__device__ float g_msum[Bc * Nc * Mc];    // [b][n][m] sum_t ms
__device__ double g_acc[5];               // cls, l1, giou, mask, n_fg
__device__ unsigned g_done;               // ticket for final write

__device__ __forceinline__ float fsigm(float x) {
    return __fdividef(1.0f, 1.0f + __expf(-x));
}

// ---------------------------------------------------------------------------
// K1: ROIAlign-style crop of gt_masks [B,M,H,W] -> gm [B,M,28*28], binarized.
// Also zeroes the loss accumulators / ticket.
// ---------------------------------------------------------------------------
__global__ void k_crop(const float* __restrict__ gt_boxes,
                       const float* __restrict__ gt_masks) {
    int bm = blockIdx.x;  // b*M + m
    if (bm == 0 && threadIdx.x < 5) g_acc[threadIdx.x] = 0.0;
    if (bm == 0 && threadIdx.x == 5) g_done = 0u;

    float x1 = gt_boxes[bm * 4 + 0];
    float y1 = gt_boxes[bm * 4 + 1];
    float x2 = gt_boxes[bm * 4 + 2];
    float y2 = gt_boxes[bm * 4 + 3];
    const float* mask = gt_masks + (size_t)bm * Hc * Wc;

    __shared__ float ssum[256];
    float acc = 0.0f;
    for (int pix = threadIdx.x; pix < TTc; pix += blockDim.x) {
        int j = pix / Tc;
        int i = pix % Tc;
        float y = y1 + ((j + 0.5f) * (y2 - y1)) / (float)Tc - 0.5f;
        float x = x1 + ((i + 0.5f) * (x2 - x1)) / (float)Tc - 0.5f;
        float y0f = floorf(y), x0f = floorf(x);
        int y0 = (int)y0f, x0 = (int)x0f;
        float fy = y - y0f, fx = x - x0f;
        float v00 = 0.f, v01 = 0.f, v10 = 0.f, v11 = 0.f;
        bool yi0 = (y0 >= 0 && y0 < Hc);
        bool yi1 = (y0 + 1 >= 0 && y0 + 1 < Hc);
        bool xi0 = (x0 >= 0 && x0 < Wc);
        bool xi1 = (x0 + 1 >= 0 && x0 + 1 < Wc);
        if (yi0 && xi0) v00 = __ldg(&mask[(size_t)y0 * Wc + x0]);
        if (yi0 && xi1) v01 = __ldg(&mask[(size_t)y0 * Wc + x0 + 1]);
        if (yi1 && xi0) v10 = __ldg(&mask[(size_t)(y0 + 1) * Wc + x0]);
        if (yi1 && xi1) v11 = __ldg(&mask[(size_t)(y0 + 1) * Wc + x0 + 1]);
        float s = v00 * (1.f - fy) * (1.f - fx) + v01 * (1.f - fy) * fx +
                  v10 * fy * (1.f - fx) + v11 * fy * fx;
        float bin = (s >= 0.5f) ? 1.0f : 0.0f;
        g_gm[bm * TTc + pix] = bin;
        acc += bin;
    }
    ssum[threadIdx.x] = acc;
    __syncthreads();
    for (int s = 128; s > 0; s >>= 1) {
        if (threadIdx.x < s) ssum[threadIdx.x] += ssum[threadIdx.x + s];
        __syncthreads();
    }
    if (threadIdx.x == 0) g_gmsum[bm] = ssum[0];
}

// ---------------------------------------------------------------------------
// K2 (hot): pure streaming mask-dot. Block = (b,n), warp m: dot + sum at gt
// class of m. float4 + __ldcs (evict-first) on the once-read mask stream.
// ---------------------------------------------------------------------------
__global__ void __launch_bounds__(512)
k_dot(const float* __restrict__ masks, const int* __restrict__ gtc) {
    int bn = blockIdx.x;  // b*N + n
    int b = bn / Nc;
    int m = threadIdx.x >> 5;
    int lane = threadIdx.x & 31;

    int c = gtc[b * Mc + m];
    const float4* mp = (const float4*)(masks + ((size_t)bn * Cc + c) * TTc);
    const float4* gp = (const float4*)(g_gm + (b * Mc + m) * TTc);
    float si = 0.f, ii = 0.f;
    #pragma unroll 7
    for (int j = lane; j < 196; j += 32) {
        float4 mv = __ldcs(&mp[j]);
        float4 gv = gp[j];
        float s0 = fsigm(mv.x), s1 = fsigm(mv.y);
        float s2 = fsigm(mv.z), s3 = fsigm(mv.w);
        si += s0 + s1 + s2 + s3;
        ii += s0 * gv.x + s1 * gv.y + s2 * gv.z + s3 * gv.w;
    }
    #pragma unroll
    for (int o = 16; o; o >>= 1) {
        si += __shfl_xor_sync(0xffffffffu, si, o);
        ii += __shfl_xor_sync(0xffffffffu, ii, o);
    }
    if (lane == 0) {
        // [b][n][m] layout: linear = bn*Mc + m
        g_inter[bn * Mc + m] = ii;
        g_msum[bn * Mc + m] = si;
    }
}

// ---------------------------------------------------------------------------
// K3: fused cost build + SimOTA match + loss. One block per batch image.
// ---------------------------------------------------------------------------
__global__ void __launch_bounds__(512)
k_matchloss(const float* __restrict__ logits, const float* __restrict__ boxes,
            const int* __restrict__ gtc, const float* __restrict__ gtb,
            const float* __restrict__ img, float* __restrict__ out) {
    __shared__ float scost[Mc * Nc];   // [m][n], 32 KB
    __shared__ int svalid[Nc];
    __shared__ int ssel[Nc];           // bitmask of selecting gts
    __shared__ double sacc[5];

    int b = blockIdx.x;
    int tid = threadIdx.x;
    int lane = tid & 31;
    int wid = tid >> 5;

    for (int i = tid; i < Nc; i += 512) { svalid[i] = 0; ssel[i] = 0; }
    if (tid < 5) sacc[tid] = 0.0;

    float i0 = img[b * 4 + 0], i1 = img[b * 4 + 1];
    float i2 = img[b * 4 + 2], i3 = img[b * 4 + 3];
    __syncthreads();

    // ---- phase 0: cost matrix (without the 1e9 valid term) + validity ----
    // e = n*16 + m; 8000 entries; whole warps are uniformly active per k.
    #pragma unroll 1
    for (int k = 0; k < 16; k++) {
        int e = tid + 512 * k;
        bool act = (e < Nc * Mc);
        bool flag = false;
        int n = e >> 4, m = e & 15;
        if (act) {
            float4 bb = ((const float4*)boxes)[b * Nc + n];
            float bx1 = bb.x, by1 = bb.y, bx2 = bb.z, by2 = bb.w;
            float cx = (bx1 + bx2) * 0.5f, cy = (by1 + by2) * 0.5f;
            float4 gb = ((const float4*)gtb)[b * Mc + m];
            float gx1 = gb.x, gy1 = gb.y, gx2 = gb.z, gy2 = gb.w;

            bool inbox = (cx > gx1) && (cx < gx2) && (cy > gy1) && (cy < gy2);
            float gcx = (gx1 + gx2) * 0.5f, gcy = (gy1 + gy2) * 0.5f;
            float gw = gx2 - gx1, gh = gy2 - gy1;
            bool inctr = (fabsf(cx - gcx) < 0.25f * gw) &&
                         (fabsf(cy - gcy) < 0.25f * gh);
            bool inboth = inbox && inctr;
            flag = inbox || inctr;

            // classification cost
            int c2 = gtc[b * Mc + m];
            float lo = logits[((size_t)b * Nc + n) * Cc + c2];
            float p = fsigm(lo);
            float neg = -logf((1.0f - p) + EPSc) * 0.75f * p * p;
            float pos = -logf(p + EPSc) * 0.25f * (1.0f - p) * (1.0f - p);
            float clsc = 2.0f * (pos - neg);

            // normalized boxes
            float nx1 = bx1 / i0, ny1 = by1 / i1, nx2 = bx2 / i2, ny2 = by2 / i3;
            float mx1 = gx1 / i0, my1 = gy1 / i1, mx2 = gx2 / i2, my2 = gy2 / i3;

            float l1c = 5.0f * (fabsf(nx1 - mx1) + fabsf(ny1 - my1) +
                                fabsf(nx2 - mx2) + fabsf(ny2 - my2));

            float ltx = fmaxf(nx1, mx1), lty = fmaxf(ny1, my1);
            float rbx = fminf(nx2, mx2), rby = fminf(ny2, my2);
            float iw = fmaxf(rbx - ltx, 0.f), ih = fmaxf(rby - lty, 0.f);
            float inter = iw * ih;
            float a1 = (nx2 - nx1) * (ny2 - ny1);
            float a2 = (mx2 - mx1) * (my2 - my1);
            float uni = a1 + a2 - inter;
            float iou = inter / (uni + EPSc);
            float ex = fmaxf(fmaxf(nx2, mx2) - fminf(nx1, mx1), 0.f);
            float ey = fmaxf(fmaxf(ny2, my2) - fminf(ny1, my1), 0.f);
            float enc = ex * ey;
            float giou = iou - (enc - uni) / (enc + EPSc);
            float giouc = 2.0f * (1.0f - giou);

            // mask dice cost
            float ii_ = g_inter[b * Nc * Mc + e];
            float si_ = g_msum[b * Nc * Mc + e];
            float mu = si_ + g_gmsum[b * Mc + m] + EPSc;
            float maskc = 5.0f * (1.0f - 2.0f * ii_ / mu);

            float cost = clsc + l1c;
            cost = cost + giouc;
            cost = cost + maskc;
            cost = cost + (inboth ? 0.0f : 1e5f);
            scost[m * Nc + n] = cost;
        }
        unsigned bal = __ballot_sync(0xffffffffu, flag);
        if (act) {
            if (lane == 0)  svalid[n] = (bal & 0xffffu) ? 1 : 0;
            if (lane == 16) svalid[n] = (bal >> 16) ? 1 : 0;
        }
    }
    __syncthreads();

    // ---- phase 1: warp per gt column. register-resident top-k ----
    {
        int m = wid;
        float4 gb = ((const float4*)gtb)[b * Mc + m];
        float gx1 = gb.x, gy1 = gb.y, gx2 = gb.z, gy2 = gb.w;
        float ga = (gx2 - gx1) * (gy2 - gy1);

        float cv[16], iv[16];
        #pragma unroll
        for (int r = 0; r < 16; r++) {
            int n = lane + 32 * r;
            if (n < Nc) {
                int v = svalid[n];
                cv[r] = scost[m * Nc + n] + (v ? 0.0f : 1e9f);
                float4 bb = ((const float4*)boxes)[b * Nc + n];
                float ltx = fmaxf(bb.x, gx1), lty = fmaxf(bb.y, gy1);
                float rbx = fminf(bb.z, gx2), rby = fminf(bb.w, gy2);
                float iw = fmaxf(rbx - ltx, 0.f), ih = fmaxf(rby - lty, 0.f);
                float inter = iw * ih;
                float a1 = (bb.z - bb.x) * (bb.w - bb.y);
                float uni = a1 + ga - inter;
                float riou = inter / (uni + EPSc);
                iv[r] = v ? riou : 0.0f;
            } else {
                cv[r] = FLT_MAX;
                iv[r] = -FLT_MAX;
            }
        }

        // dyn_k = clamp(trunc(sum of top-10 ious), 1, 10)
        float ksum = 0.0f;
        for (int k = 0; k < CANDK; k++) {
            float best = -FLT_MAX; int bi = INT_MAX;
            #pragma unroll
            for (int r = 0; r < 16; r++) {
                if (iv[r] > best) { best = iv[r]; bi = lane + 32 * r; }
            }
            #pragma unroll
            for (int o = 16; o; o >>= 1) {
                float ov = __shfl_xor_sync(0xffffffffu, best, o);
                int oi = __shfl_xor_sync(0xffffffffu, bi, o);
                if (ov > best || (ov == best && oi < bi)) { best = ov; bi = oi; }
            }
            ksum += best;
            int rr = bi >> 5, ll = bi & 31;
            #pragma unroll
            for (int r = 0; r < 16; r++)
                if (r == rr && ll == lane) iv[r] = -FLT_MAX;
        }
        int dyn = (int)ksum;
        if (dyn < 1) dyn = 1;
        if (dyn > CANDK) dyn = CANDK;

        // dyn lowest-cost anchors; mark in shared bitmask
        for (int k = 0; k < CANDK; k++) {
            float best = FLT_MAX; int bi = INT_MAX;
            #pragma unroll
            for (int r = 0; r < 16; r++) {
                if (cv[r] < best) { best = cv[r]; bi = lane + 32 * r; }
            }
            #pragma unroll
            for (int o = 16; o; o >>= 1) {
                float ov = __shfl_xor_sync(0xffffffffu, best, o);
                int oi = __shfl_xor_sync(0xffffffffu, bi, o);
                if (ov < best || (ov == best && oi < bi)) { best = ov; bi = oi; }
            }
            if (lane == 0 && k < dyn) atomicOr(&ssel[bi], 1 << m);
            int rr = bi >> 5, ll = bi & 31;
            #pragma unroll
            for (int r = 0; r < 16; r++)
                if (r == rr && ll == lane) cv[r] = FLT_MAX;
        }
    }
    __syncthreads();

    // ---- phase 2: resolve matching, losses. warp handles 32 anchors ----
    for (int j = 0; j < 32; j++) {
        int n = wid * 32 + j;
        if (n >= Nc) break;
        int sel = ssel[n];
        int valid = svalid[n];
        int cnt = __popc(sel);
        if (cnt == 0 || !valid) continue;

        int matched;
        if (cnt > 1) {
            float v = (lane < Mc) ? scost[lane * Nc + n] : FLT_MAX;
            int bi = (lane < Mc) ? lane : INT_MAX;
            #pragma unroll
            for (int o = 16; o; o >>= 1) {
                float ov = __shfl_xor_sync(0xffffffffu, v, o);
                int oi = __shfl_xor_sync(0xffffffffu, bi, o);
                if (ov < v || (ov == v && oi < bi)) { v = ov; bi = oi; }
            }
            matched = bi;
        } else {
            matched = __ffs(sel) - 1;
        }

        int tcls = gtc[b * Mc + matched];
        float fsum = 0.0f;
        for (int c = lane; c < Cc; c += 32) {
            float l = logits[((size_t)b * Nc + n) * Cc + c];
            float tgt = (c == tcls) ? 1.0f : 0.0f;
            float p = fsigm(l);
            float ce = fmaxf(l, 0.0f) - l * tgt + log1pf(__expf(-fabsf(l)));
            float pt = p * tgt + (1.0f - p) * (1.0f - tgt);
            float om = 1.0f - pt;
            float w = 0.25f * tgt + 0.75f * (1.0f - tgt);
            fsum += ce * om * om * w;
        }
        #pragma unroll
        for (int o = 16; o; o >>= 1) fsum += __shfl_xor_sync(0xffffffffu, fsum, o);

        if (lane == 0) {
            float4 bb = ((const float4*)boxes)[b * Nc + n];
            float nx1 = bb.x / i0, ny1 = bb.y / i1, nx2 = bb.z / i2, ny2 = bb.w / i3;
            int gm_i = b * Mc + matched;
            float4 gb = ((const float4*)gtb)[gm_i];
            float mx1 = gb.x / i0, my1 = gb.y / i1, mx2 = gb.z / i2, my2 = gb.w / i3;

            float l1v = fabsf(nx1 - mx1) + fabsf(ny1 - my1) +
                        fabsf(nx2 - mx2) + fabsf(ny2 - my2);

            float ltx = fmaxf(nx1, mx1), lty = fmaxf(ny1, my1);
            float rbx = fminf(nx2, mx2), rby = fminf(ny2, my2);
            float iw = fmaxf(rbx - ltx, 0.f), ih = fmaxf(rby - lty, 0.f);
            float inter = iw * ih;
            float a1 = (nx2 - nx1) * (ny2 - ny1);
            float a2 = (mx2 - mx1) * (my2 - my1);
            float uni = a1 + a2 - inter;
            float iou = inter / (uni + EPSc);
            float ex = fmaxf(fmaxf(nx2, mx2) - fminf(nx1, mx1), 0.f);
            float ey = fmaxf(fmaxf(ny2, my2) - fminf(ny1, my1), 0.f);
            float enc = ex * ey;
            float giou = iou - (enc - uni) / (enc + EPSc);
            float gv = 1.0f - giou;

            float mi = g_inter[(b * Nc + n) * Mc + matched];
            float msv = g_msum[(b * Nc + n) * Mc + matched];
            float mu = msv + g_gmsum[gm_i] + EPSc;
            float mkv = 1.0f - 2.0f * mi / mu;

            atomicAdd(&sacc[0], (double)fsum);
            atomicAdd(&sacc[1], (double)l1v);
            atomicAdd(&sacc[2], (double)gv);
            atomicAdd(&sacc[3], (double)mkv);
            atomicAdd(&sacc[4], 1.0);
        }
    }

    __syncthreads();
    if (tid < 5) atomicAdd(&g_acc[tid], sacc[tid]);
    __syncthreads();
    if (tid == 0) {
        __threadfence();
        unsigned ticket = atomicAdd(&g_done, 1u);
        if (ticket == gridDim.x - 1) {
            __threadfence();
            double nt = g_acc[4];
            out[0] = (float)(2.0 * g_acc[0] / nt);
            out[1] = (float)(5.0 * g_acc[1] / nt);
            out[2] = (float)(2.0 * g_acc[2] / nt);
            out[3] = (float)(5.0 * g_acc[3] / nt);
        }
    }
}

extern "C" void kernel_launch(void* const* d_in, const int* in_sizes, int n_in,
                              void* d_out, int out_size) {
    const float* pred_logits = (const float*)d_in[0];
    const float* pred_boxes  = (const float*)d_in[1];
    const float* pred_masks  = (const float*)d_in[2];
    const int*   gt_classes  = (const int*)d_in[3];
    const float* gt_boxes    = (const float*)d_in[4];
    const float* gt_masks    = (const float*)d_in[5];
    const float* image_size  = (const float*)d_in[6];
    float* out = (float*)d_out;

    k_crop<<<Bc * Mc, 256>>>(gt_boxes, gt_masks);
    k_dot<<<Bc * Nc, 512>>>(pred_masks, gt_classes);
    k_matchloss<<<Bc, 512>>>(pred_logits, pred_boxes, gt_classes, gt_boxes,
                             image_size, out);
}

// round 4
// speedup vs baseline: 1.3858x; 1.3858x over previous
#include <cuda_runtime.h>
#include <cfloat>
#include <climits>
#include <math.h>

// Problem constants
#define Bc 4
#define Nc 500
#define Cc 80
#define Tc 28
#define TTc 784
#define Mc 16
#define Hc 800
#define Wc 800
#define EPSc 1e-8f
#define CANDK 10
#define GMW 25   // 784 bits -> 25 words

// Scratch (device globals; no allocation allowed)
__device__ unsigned g_gmb[Bc * Mc * GMW];  // binarized gt masks, bit-packed
__device__ float g_gmsum[Bc * Mc];         // per gt mask sums
__device__ float g_intT[Bc * Mc * Nc];     // [b][m][n] sum_t ms*gm (transposed)
__device__ float g_msumT[Bc * Mc * Nc];    // [b][m][n] sum_t ms
__device__ float g_costT[Bc * Mc * Nc];    // [b][m][n] full cost
__device__ int   g_valid[Bc * Nc];         // per-anchor validity
__device__ unsigned g_selmask[Bc * Nc];    // bit m set if gt m selected anchor n
__device__ double g_acc[5];                // cls, l1, giou, mask, n_fg
__device__ unsigned g_done;                // ticket for final write

__device__ __forceinline__ float fsigm(float x) {
    return __fdividef(1.0f, 1.0f + __expf(-x));
}

// ---------------------------------------------------------------------------
// K1: crop+binarize gt masks -> bitmask. One pixel per thread (800 thr/block).
// Also zeroes accumulators / ticket / selection masks.
// ---------------------------------------------------------------------------
__global__ void __launch_bounds__(800)
k_crop(const float* __restrict__ gt_boxes, const float* __restrict__ gt_masks) {
    int bm = blockIdx.x;  // b*M + m
    int tid = threadIdx.x;
    int lane = tid & 31;
    int w = tid >> 5;     // warp id 0..24

    // housekeeping zeroing (spread across blocks)
    {
        int z = bm * 32 + lane;
        if (w == 0 && z < Bc * Nc) g_selmask[z] = 0u;
        if (bm == 0 && w == 1) {
            if (lane < 5) g_acc[lane] = 0.0;
            if (lane == 5) g_done = 0u;
        }
    }

    float4 gb = ((const float4*)gt_boxes)[bm];
    float x1 = gb.x, y1 = gb.y, x2 = gb.z, y2 = gb.w;
    const float* mask = gt_masks + (size_t)bm * Hc * Wc;

    float bin = 0.0f;
    if (tid < TTc) {
        int j = tid / Tc;
        int i = tid % Tc;
        float y = y1 + ((j + 0.5f) * (y2 - y1)) / (float)Tc - 0.5f;
        float x = x1 + ((i + 0.5f) * (x2 - x1)) / (float)Tc - 0.5f;
        float y0f = floorf(y), x0f = floorf(x);
        int y0 = (int)y0f, x0 = (int)x0f;
        float fy = y - y0f, fx = x - x0f;
        float v00 = 0.f, v01 = 0.f, v10 = 0.f, v11 = 0.f;
        bool yi0 = (y0 >= 0 && y0 < Hc);
        bool yi1 = (y0 + 1 >= 0 && y0 + 1 < Hc);
        bool xi0 = (x0 >= 0 && x0 < Wc);
        bool xi1 = (x0 + 1 >= 0 && x0 + 1 < Wc);
        if (yi0 && xi0) v00 = __ldg(&mask[(size_t)y0 * Wc + x0]);
        if (yi0 && xi1) v01 = __ldg(&mask[(size_t)y0 * Wc + x0 + 1]);
        if (yi1 && xi0) v10 = __ldg(&mask[(size_t)(y0 + 1) * Wc + x0]);
        if (yi1 && xi1) v11 = __ldg(&mask[(size_t)(y0 + 1) * Wc + x0 + 1]);
        float s = v00 * (1.f - fy) * (1.f - fx) + v01 * (1.f - fy) * fx +
                  v10 * fy * (1.f - fx) + v11 * fy * fx;
        bin = (s >= 0.5f) ? 1.0f : 0.0f;
    }
    unsigned bits = __ballot_sync(0xffffffffu, bin > 0.0f);
    __shared__ int scnt[GMW];
    if (lane == 0) {
        g_gmb[bm * GMW + w] = bits;
        scnt[w] = __popc(bits);
    }
    __syncthreads();
    if (tid == 0) {
        int tot = 0;
        #pragma unroll
        for (int k = 0; k < GMW; k++) tot += scnt[k];
        g_gmsum[bm] = (float)tot;
    }
}

// ---------------------------------------------------------------------------
// K2 (hot): streaming mask-dot. Block = (b,n), warp m: sigmoid dot + sum at
// gt class of m against bit-packed gm. Epilogue: per-anchor validity.
// ---------------------------------------------------------------------------
__global__ void __launch_bounds__(512)
k_dot(const float* __restrict__ masks, const int* __restrict__ gtc,
      const float* __restrict__ boxes, const float* __restrict__ gtb) {
    int bn = blockIdx.x;  // b*N + n
    int b = bn / Nc;
    int m = threadIdx.x >> 5;
    int lane = threadIdx.x & 31;
    int bm = b * Mc + m;

    __shared__ unsigned sflag;
    if (threadIdx.x == 0) sflag = 0u;
    __syncthreads();

    int c = gtc[bm];
    const float4* mp = (const float4*)(masks + ((size_t)bn * Cc + c) * TTc);
    const unsigned* gw = &g_gmb[bm * GMW];
    float si = 0.f, ii = 0.f;
    #pragma unroll 7
    for (int j = lane; j < 196; j += 32) {
        float4 mv = __ldcs(&mp[j]);
        unsigned nib = (__ldg(&gw[j >> 3]) >> ((j & 7) * 4)) & 0xFu;
        float s0 = fsigm(mv.x), s1 = fsigm(mv.y);
        float s2 = fsigm(mv.z), s3 = fsigm(mv.w);
        si += s0 + s1 + s2 + s3;
        ii += ((nib & 1u) ? s0 : 0.f) + ((nib & 2u) ? s1 : 0.f) +
              ((nib & 4u) ? s2 : 0.f) + ((nib & 8u) ? s3 : 0.f);
    }
    #pragma unroll
    for (int o = 16; o; o >>= 1) {
        si += __shfl_xor_sync(0xffffffffu, si, o);
        ii += __shfl_xor_sync(0xffffffffu, ii, o);
    }
    if (lane == 0) {
        int n = bn % Nc;
        g_intT[bm * Nc + n] = ii;
        g_msumT[bm * Nc + n] = si;
        // validity flag for (n, m)
        float4 bb = ((const float4*)boxes)[bn];
        float cx = (bb.x + bb.z) * 0.5f, cy = (bb.y + bb.w) * 0.5f;
        float4 gbv = ((const float4*)gtb)[bm];
        bool inbox = (cx > gbv.x) && (cx < gbv.z) && (cy > gbv.y) && (cy < gbv.w);
        float gcx = (gbv.x + gbv.z) * 0.5f, gcy = (gbv.y + gbv.w) * 0.5f;
        bool inctr = (fabsf(cx - gcx) < 0.25f * (gbv.z - gbv.x)) &&
                     (fabsf(cy - gcy) < 0.25f * (gbv.w - gbv.y));
        if (inbox || inctr) atomicOr(&sflag, 1u);
    }
    __syncthreads();
    if (threadIdx.x == 0) g_valid[bn] = (sflag != 0u) ? 1 : 0;
}

// ---------------------------------------------------------------------------
// K3: warp per (b,m) column. Builds its cost column (stored transposed for
// k_loss), computes dyn_k from top-10 IoUs, selects dyn_k lowest-cost anchors
// into g_selmask bitmask. All tie-breaks lowest-index (lax.top_k stable).
// ---------------------------------------------------------------------------
__global__ void __launch_bounds__(32)
k_match(const float* __restrict__ logits, const float* __restrict__ boxes,
        const int* __restrict__ gtc, const float* __restrict__ gtb,
        const float* __restrict__ img) {
    int bm = blockIdx.x;  // b*M + m
    int b = bm / Mc;
    int m = bm % Mc;
    int lane = threadIdx.x;

    float4 gb = ((const float4*)gtb)[bm];
    float gx1 = gb.x, gy1 = gb.y, gx2 = gb.z, gy2 = gb.w;
    float ga = (gx2 - gx1) * (gy2 - gy1);
    float gcx = (gx1 + gx2) * 0.5f, gcy = (gy1 + gy2) * 0.5f;
    float gw_ = gx2 - gx1, gh = gy2 - gy1;
    int c2 = gtc[bm];
    float i0 = img[b * 4 + 0], i1 = img[b * 4 + 1];
    float i2 = img[b * 4 + 2], i3 = img[b * 4 + 3];
    float mx1 = gx1 / i0, my1 = gy1 / i1, mx2 = gx2 / i2, my2 = gy2 / i3;
    float gmsum = g_gmsum[bm];

    float cv[16], iv[16];
    #pragma unroll
    for (int r = 0; r < 16; r++) {
        int n = lane + 32 * r;
        if (n < Nc) {
            int bnn = b * Nc + n;
            float4 bb = ((const float4*)boxes)[bnn];
            float bx1 = bb.x, by1 = bb.y, bx2 = bb.z, by2 = bb.w;
            float cx = (bx1 + bx2) * 0.5f, cy = (by1 + by2) * 0.5f;
            bool inbox = (cx > gx1) && (cx < gx2) && (cy > gy1) && (cy < gy2);
            bool inctr = (fabsf(cx - gcx) < 0.25f * gw_) &&
                         (fabsf(cy - gcy) < 0.25f * gh);
            bool inboth = inbox && inctr;
            int valid = g_valid[bnn];

            float lo = __ldg(&logits[(size_t)bnn * Cc + c2]);
            float p = fsigm(lo);
            float neg = -logf((1.0f - p) + EPSc) * 0.75f * p * p;
            float pos = -logf(p + EPSc) * 0.25f * (1.0f - p) * (1.0f - p);
            float clsc = 2.0f * (pos - neg);

            float nx1 = bx1 / i0, ny1 = by1 / i1, nx2 = bx2 / i2, ny2 = by2 / i3;
            float l1c = 5.0f * (fabsf(nx1 - mx1) + fabsf(ny1 - my1) +
                                fabsf(nx2 - mx2) + fabsf(ny2 - my2));

            float ltx = fmaxf(nx1, mx1), lty = fmaxf(ny1, my1);
            float rbx = fminf(nx2, mx2), rby = fminf(ny2, my2);
            float iw = fmaxf(rbx - ltx, 0.f), ih = fmaxf(rby - lty, 0.f);
            float inter = iw * ih;
            float a1 = (nx2 - nx1) * (ny2 - ny1);
            float a2 = (mx2 - mx1) * (my2 - my1);
            float uni = a1 + a2 - inter;
            float iou = inter / (uni + EPSc);
            float ex = fmaxf(fmaxf(nx2, mx2) - fminf(nx1, mx1), 0.f);
            float ey = fmaxf(fmaxf(ny2, my2) - fminf(ny1, my1), 0.f);
            float enc = ex * ey;
            float giou = iou - (enc - uni) / (enc + EPSc);
            float giouc = 2.0f * (1.0f - giou);

            float ii_ = g_intT[bm * Nc + n];
            float si_ = g_msumT[bm * Nc + n];
            float mu = si_ + gmsum + EPSc;
            float maskc = 5.0f * (1.0f - 2.0f * ii_ / mu);

            float cost = clsc + l1c;
            cost = cost + giouc;
            cost = cost + maskc;
            cost = cost + (inboth ? 0.0f : 1e5f);
            cost = cost + (valid ? 0.0f : 1e9f);
            g_costT[bm * Nc + n] = cost;
            cv[r] = cost;

            // raw pixel-space IoU, valid-gated
            float rltx = fmaxf(bx1, gx1), rlty = fmaxf(by1, gy1);
            float rrbx = fminf(bx2, gx2), rrby = fminf(by2, gy2);
            float riw = fmaxf(rrbx - rltx, 0.f), rih = fmaxf(rrby - rlty, 0.f);
            float rinter = riw * rih;
            float ra1 = (bx2 - bx1) * (by2 - by1);
            float runi = ra1 + ga - rinter;
            float riou = rinter / (runi + EPSc);
            iv[r] = valid ? riou : 0.0f;
        } else {
            cv[r] = FLT_MAX;
            iv[r] = -FLT_MAX;
        }
    }

    // dyn_k = clamp(trunc(sum of top-10 ious), 1, 10)
    float ksum = 0.0f;
    for (int k = 0; k < CANDK; k++) {
        float best = -FLT_MAX; int bi = INT_MAX;
        #pragma unroll
        for (int r = 0; r < 16; r++) {
            if (iv[r] > best) { best = iv[r]; bi = lane + 32 * r; }
        }
        #pragma unroll
        for (int o = 16; o; o >>= 1) {
            float ov = __shfl_xor_sync(0xffffffffu, best, o);
            int oi = __shfl_xor_sync(0xffffffffu, bi, o);
            if (ov > best || (ov == best && oi < bi)) { best = ov; bi = oi; }
        }
        ksum += best;
        int rr = bi >> 5, ll = bi & 31;
        #pragma unroll
        for (int r = 0; r < 16; r++)
            if (r == rr && ll == lane) iv[r] = -FLT_MAX;
    }
    int dyn = (int)ksum;
    if (dyn < 1) dyn = 1;
    if (dyn > CANDK) dyn = CANDK;

    // dyn lowest-cost anchors -> bit m in g_selmask
    for (int k = 0; k < CANDK; k++) {
        float best = FLT_MAX; int bi = INT_MAX;
        #pragma unroll
        for (int r = 0; r < 16; r++) {
            if (cv[r] < best) { best = cv[r]; bi = lane + 32 * r; }
        }
        #pragma unroll
        for (int o = 16; o; o >>= 1) {
            float ov = __shfl_xor_sync(0xffffffffu, best, o);
            int oi = __shfl_xor_sync(0xffffffffu, bi, o);
            if (ov < best || (ov == best && oi < bi)) { best = ov; bi = oi; }
        }
        if (lane == 0 && k < dyn) atomicOr(&g_selmask[b * Nc + bi], 1u << m);
        int rr = bi >> 5, ll = bi & 31;
        #pragma unroll
        for (int r = 0; r < 16; r++)
            if (r == rr && ll == lane) cv[r] = FLT_MAX;
    }
}

// ---------------------------------------------------------------------------
// K4: warp per (b,n). Membership = one int + popc. Losses -> accumulators;
// last block writes the output.
// ---------------------------------------------------------------------------
__global__ void __launch_bounds__(256)
k_loss(const float* __restrict__ logits, const float* __restrict__ boxes,
       const int* __restrict__ gtc, const float* __restrict__ gtb,
       const float* __restrict__ img, float* __restrict__ out) {
    __shared__ double sacc[5];
    int tid = threadIdx.x;
    if (tid < 5) sacc[tid] = 0.0;
    __syncthreads();

    int wid = tid >> 5;
    int lane = tid & 31;
    int g = blockIdx.x * 8 + wid;  // b*N + n
    int b = g / Nc;
    int n = g % Nc;

    unsigned sel = g_selmask[g];
    int valid = g_valid[g];
    int cnt = __popc(sel);
    int fg = (cnt > 0) && valid;

    if (fg) {
        int matched;
        if (cnt > 1) {
            float v = (lane < Mc) ? g_costT[(b * Mc + lane) * Nc + n] : FLT_MAX;
            int bi = (lane < Mc) ? lane : INT_MAX;
            #pragma unroll
            for (int o = 16; o; o >>= 1) {
                float ov = __shfl_xor_sync(0xffffffffu, v, o);
                int oi = __shfl_xor_sync(0xffffffffu, bi, o);
                if (ov < v || (ov == v && oi < bi)) { v = ov; bi = oi; }
            }
            matched = bi;
        } else {
            matched = __ffs(sel) - 1;
        }

        int gm_i = b * Mc + matched;
        int tcls = gtc[gm_i];
        float fsum = 0.0f;
        #pragma unroll
        for (int k = 0; k < 3; k++) {
            int c = lane + 32 * k;
            if (c < Cc) {
                float l = logits[(size_t)g * Cc + c];
                float tgt = (c == tcls) ? 1.0f : 0.0f;
                float p = fsigm(l);
                float ce = fmaxf(l, 0.0f) - l * tgt + log1pf(__expf(-fabsf(l)));
                float pt = p * tgt + (1.0f - p) * (1.0f - tgt);
                float om = 1.0f - pt;
                float w = 0.25f * tgt + 0.75f * (1.0f - tgt);
                fsum += ce * om * om * w;
            }
        }
        #pragma unroll
        for (int o = 16; o; o >>= 1) fsum += __shfl_xor_sync(0xffffffffu, fsum, o);

        if (lane == 0) {
            float i0 = img[b * 4 + 0], i1 = img[b * 4 + 1];
            float i2 = img[b * 4 + 2], i3 = img[b * 4 + 3];
            float4 bb = ((const float4*)boxes)[g];
            float nx1 = bb.x / i0, ny1 = bb.y / i1, nx2 = bb.z / i2, ny2 = bb.w / i3;
            float4 gbv = ((const float4*)gtb)[gm_i];
            float mx1 = gbv.x / i0, my1 = gbv.y / i1, mx2 = gbv.z / i2, my2 = gbv.w / i3;

            float l1v = fabsf(nx1 - mx1) + fabsf(ny1 - my1) +
                        fabsf(nx2 - mx2) + fabsf(ny2 - my2);

            float ltx = fmaxf(nx1, mx1), lty = fmaxf(ny1, my1);
            float rbx = fminf(nx2, mx2), rby = fminf(ny2, my2);
            float iw = fmaxf(rbx - ltx, 0.f), ih = fmaxf(rby - lty, 0.f);
            float inter = iw * ih;
            float a1 = (nx2 - nx1) * (ny2 - ny1);
            float a2 = (mx2 - mx1) * (my2 - my1);
            float uni = a1 + a2 - inter;
            float iou = inter / (uni + EPSc);
            float ex = fmaxf(fmaxf(nx2, mx2) - fminf(nx1, mx1), 0.f);
            float ey = fmaxf(fmaxf(ny2, my2) - fminf(ny1, my1), 0.f);
            float enc = ex * ey;
            float giou = iou - (enc - uni) / (enc + EPSc);
            float gv = 1.0f - giou;

            float mi = g_intT[gm_i * Nc + n];
            float msv = g_msumT[gm_i * Nc + n];
            float mu = msv + g_gmsum[gm_i] + EPSc;
            float mkv = 1.0f - 2.0f * mi / mu;

            atomicAdd(&sacc[0], (double)fsum);
            atomicAdd(&sacc[1], (double)l1v);
            atomicAdd(&sacc[2], (double)gv);
            atomicAdd(&sacc[3], (double)mkv);
            atomicAdd(&sacc[4], 1.0);
        }
    }
    __syncthreads();
    if (tid < 5) atomicAdd(&g_acc[tid], sacc[tid]);
    __syncthreads();
    if (tid == 0) {
        __threadfence();
        unsigned ticket = atomicAdd(&g_done, 1u);
        if (ticket == gridDim.x - 1) {
            __threadfence();
            double nt = g_acc[4];
            out[0] = (float)(2.0 * g_acc[0] / nt);
            out[1] = (float)(5.0 * g_acc[1] / nt);
            out[2] = (float)(2.0 * g_acc[2] / nt);
            out[3] = (float)(5.0 * g_acc[3] / nt);
        }
    }
}

extern "C" void kernel_launch(void* const* d_in, const int* in_sizes, int n_in,
                              void* d_out, int out_size) {
    const float* pred_logits = (const float*)d_in[0];
    const float* pred_boxes  = (const float*)d_in[1];
    const float* pred_masks  = (const float*)d_in[2];
    const int*   gt_classes  = (const int*)d_in[3];
    const float* gt_boxes    = (const float*)d_in[4];
    const float* gt_masks    = (const float*)d_in[5];
    const float* image_size  = (const float*)d_in[6];
    float* out = (float*)d_out;

    k_crop<<<Bc * Mc, 800>>>(gt_boxes, gt_masks);
    k_dot<<<Bc * Nc, 512>>>(pred_masks, gt_classes, pred_boxes, gt_boxes);
    k_match<<<Bc * Mc, 32>>>(pred_logits, pred_boxes, gt_classes, gt_boxes,
                             image_size);
    k_loss<<<(Bc * Nc) / 8, 256>>>(pred_logits, pred_boxes, gt_classes,
                                   gt_boxes, image_size, out);
}

// round 6
// speedup vs baseline: 1.4807x; 1.0685x over previous
#include <cuda_runtime.h>
#include <cfloat>
#include <climits>
#include <math.h>

// Problem constants
#define Bc 4
#define Nc 500
#define Cc 80
#define Tc 28
#define TTc 784
#define Mc 16
#define Hc 800
#define Wc 800
#define EPSc 1e-8f
#define CANDK 10

#define COSTGRID 592   // 148 SMs x 4 blocks: one wave, loop over anchors

// Scratch (device globals; no allocation allowed)
__device__ float g_gm[Bc * Mc * TTc];     // cropped+binarized gt masks
__device__ float g_gmsum[Bc * Mc];        // per gt mask sums
__device__ float g_inter[Bc * Nc * Mc];   // [bn][m] sum_t ms*gm
__device__ float g_msum[Bc * Nc * Mc];    // [bn][m] sum_t ms
__device__ float g_cost[Bc * Nc * Mc];    // [bn][m] full SimOTA cost
__device__ float g_ious[Bc * Nc * Mc];    // [bn][m] raw IoU (valid-gated)
__device__ int   g_valid[Bc * Nc];        // per-anchor validity
__device__ unsigned g_selmask[Bc * Nc];   // bit m set if gt m selected anchor n
__device__ double g_acc[5];               // cls, l1, giou, mask, n_fg
__device__ unsigned g_done;               // ticket for final write

__device__ __forceinline__ float fsigm(float x) {
    return __fdividef(1.0f, 1.0f + __expf(-x));
}

// ---------------------------------------------------------------------------
// K1: crop+binarize gt masks. One pixel per thread (800 thr/block).
// Also zeroes accumulators / ticket / selection masks.
// ---------------------------------------------------------------------------
__global__ void __launch_bounds__(800)
k_crop(const float* __restrict__ gt_boxes, const float* __restrict__ gt_masks) {
    int bm = blockIdx.x;  // b*M + m
    int tid = threadIdx.x;
    int lane = tid & 31;
    int w = tid >> 5;     // warp id 0..24

    // housekeeping zeroing (spread across blocks)
    {
        int z = bm * 32 + lane;
        if (w == 0 && z < Bc * Nc) g_selmask[z] = 0u;
        if (bm == 0 && w == 1) {
            if (lane < 5) g_acc[lane] = 0.0;
            if (lane == 5) g_done = 0u;
        }
    }

    float4 gb = ((const float4*)gt_boxes)[bm];
    float x1 = gb.x, y1 = gb.y, x2 = gb.z, y2 = gb.w;
    const float* mask = gt_masks + (size_t)bm * Hc * Wc;

    __shared__ float scnt;
    if (tid == 0) scnt = 0.0f;
    __syncthreads();

    float bin = 0.0f;
    if (tid < TTc) {
        int j = tid / Tc;
        int i = tid % Tc;
        float y = y1 + ((j + 0.5f) * (y2 - y1)) / (float)Tc - 0.5f;
        float x = x1 + ((i + 0.5f) * (x2 - x1)) / (float)Tc - 0.5f;
        float y0f = floorf(y), x0f = floorf(x);
        int y0 = (int)y0f, x0 = (int)x0f;
        float fy = y - y0f, fx = x - x0f;
        float v00 = 0.f, v01 = 0.f, v10 = 0.f, v11 = 0.f;
        bool yi0 = (y0 >= 0 && y0 < Hc);
        bool yi1 = (y0 + 1 >= 0 && y0 + 1 < Hc);
        bool xi0 = (x0 >= 0 && x0 < Wc);
        bool xi1 = (x0 + 1 >= 0 && x0 + 1 < Wc);
        if (yi0 && xi0) v00 = __ldg(&mask[(size_t)y0 * Wc + x0]);
        if (yi0 && xi1) v01 = __ldg(&mask[(size_t)y0 * Wc + x0 + 1]);
        if (yi1 && xi0) v10 = __ldg(&mask[(size_t)(y0 + 1) * Wc + x0]);
        if (yi1 && xi1) v11 = __ldg(&mask[(size_t)(y0 + 1) * Wc + x0 + 1]);
        float s = v00 * (1.f - fy) * (1.f - fx) + v01 * (1.f - fy) * fx +
                  v10 * fy * (1.f - fx) + v11 * fy * fx;
        bin = (s >= 0.5f) ? 1.0f : 0.0f;
        g_gm[bm * TTc + tid] = bin;
    }
    float acc = bin;
    #pragma unroll
    for (int o = 16; o; o >>= 1) acc += __shfl_xor_sync(0xffffffffu, acc, o);
    if (lane == 0 && acc != 0.0f) atomicAdd(&scnt, acc);
    __syncthreads();
    if (tid == 0) g_gmsum[bm] = scnt;
}

// ---------------------------------------------------------------------------
// K2 (hot): even-grid streaming. 592 blocks loop over 2000 anchors.
// Warp m: sigmoid mask dot + sum at gt class m. Threads 0..15: cost epilogue.
// ---------------------------------------------------------------------------
__global__ void __launch_bounds__(512)
k_cost(const float* __restrict__ logits, const float* __restrict__ boxes,
       const float* __restrict__ masks, const int* __restrict__ gtc,
       const float* __restrict__ gtb, const float* __restrict__ img) {
    int tid = threadIdx.x;
    int wid = tid >> 5;
    int lane = tid & 31;

    __shared__ float s_i[Mc], s_s[Mc];

    for (int bn = blockIdx.x; bn < Bc * Nc; bn += COSTGRID) {
        int b = bn / Nc;
        {
            int m = wid;
            int c = gtc[b * Mc + m];
            const float4* mp = (const float4*)(masks + ((size_t)bn * Cc + c) * TTc);
            const float4* gp = (const float4*)(g_gm + (b * Mc + m) * TTc);
            float si = 0.f, ii = 0.f;
            #pragma unroll 7
            for (int j = lane; j < 196; j += 32) {
                float4 mv = __ldcs(&mp[j]);
                float4 gv = __ldg(&gp[j]);
                float s0 = fsigm(mv.x), s1 = fsigm(mv.y);
                float s2 = fsigm(mv.z), s3 = fsigm(mv.w);
                si += s0 + s1 + s2 + s3;
                ii += s0 * gv.x + s1 * gv.y + s2 * gv.z + s3 * gv.w;
            }
            #pragma unroll
            for (int o = 16; o; o >>= 1) {
                si += __shfl_xor_sync(0xffffffffu, si, o);
                ii += __shfl_xor_sync(0xffffffffu, ii, o);
            }
            if (lane == 0) {
                s_i[m] = ii;
                s_s[m] = si;
                g_inter[bn * Mc + m] = ii;
                g_msum[bn * Mc + m] = si;
            }
        }
        __syncthreads();

        if (tid < Mc) {
            int m = tid;
            float4 bb = ((const float4*)boxes)[bn];
            float bx1 = bb.x, by1 = bb.y, bx2 = bb.z, by2 = bb.w;
            float cx = (bx1 + bx2) * 0.5f, cy = (by1 + by2) * 0.5f;
            float4 gb = ((const float4*)gtb)[b * Mc + m];
            float gx1 = gb.x, gy1 = gb.y, gx2 = gb.z, gy2 = gb.w;

            bool inbox = (cx > gx1) && (cx < gx2) && (cy > gy1) && (cy < gy2);
            float gcx = (gx1 + gx2) * 0.5f, gcy = (gy1 + gy2) * 0.5f;
            float gw = gx2 - gx1, gh = gy2 - gy1;
            bool inctr = (fabsf(cx - gcx) < 0.25f * gw) &&
                         (fabsf(cy - gcy) < 0.25f * gh);
            bool inboth = inbox && inctr;
            unsigned ball = __ballot_sync(0xffffu, inbox || inctr);
            bool valid = (ball != 0u);

            int c2 = gtc[b * Mc + m];
            float lo = logits[(size_t)bn * Cc + c2];
            float p = fsigm(lo);
            float neg = -logf((1.0f - p) + EPSc) * 0.75f * p * p;
            float pos = -logf(p + EPSc) * 0.25f * (1.0f - p) * (1.0f - p);
            float clsc = 2.0f * (pos - neg);

            float i0 = img[b * 4 + 0], i1 = img[b * 4 + 1];
            float i2 = img[b * 4 + 2], i3 = img[b * 4 + 3];
            float nx1 = bx1 / i0, ny1 = by1 / i1, nx2 = bx2 / i2, ny2 = by2 / i3;
            float mx1 = gx1 / i0, my1 = gy1 / i1, mx2 = gx2 / i2, my2 = gy2 / i3;

            float l1c = 5.0f * (fabsf(nx1 - mx1) + fabsf(ny1 - my1) +
                                fabsf(nx2 - mx2) + fabsf(ny2 - my2));

            float ltx = fmaxf(nx1, mx1), lty = fmaxf(ny1, my1);
            float rbx = fminf(nx2, mx2), rby = fminf(ny2, my2);
            float iw = fmaxf(rbx - ltx, 0.f), ih = fmaxf(rby - lty, 0.f);
            float inter = iw * ih;
            float a1 = (nx2 - nx1) * (ny2 - ny1);
            float a2 = (mx2 - mx1) * (my2 - my1);
            float uni = a1 + a2 - inter;
            float iou = inter / (uni + EPSc);
            float ex = fmaxf(fmaxf(nx2, mx2) - fminf(nx1, mx1), 0.f);
            float ey = fmaxf(fmaxf(ny2, my2) - fminf(ny1, my1), 0.f);
            float enc = ex * ey;
            float giou = iou - (enc - uni) / (enc + EPSc);
            float giouc = 2.0f * (1.0f - giou);

            float mu = s_s[m] + g_gmsum[b * Mc + m] + EPSc;
            float maskc = 5.0f * (1.0f - 2.0f * s_i[m] / mu);

            float cost = clsc + l1c;
            cost = cost + giouc;
            cost = cost + maskc;
            cost = cost + (inboth ? 0.0f : 1e5f);
            cost = cost + (valid ? 0.0f : 1e9f);
            g_cost[bn * Mc + m] = cost;

            float rltx = fmaxf(bx1, gx1), rlty = fmaxf(by1, gy1);
            float rrbx = fminf(bx2, gx2), rrby = fminf(by2, gy2);
            float riw = fmaxf(rrbx - rltx, 0.f), rih = fmaxf(rrby - rlty, 0.f);
            float rinter = riw * rih;
            float ra1 = (bx2 - bx1) * (by2 - by1);
            float ra2 = (gx2 - gx1) * (gy2 - gy1);
            float runi = ra1 + ra2 - rinter;
            float riou = rinter / (runi + EPSc);
            g_ious[bn * Mc + m] = riou * (valid ? 1.0f : 0.0f);

            if (m == 0) g_valid[bn] = valid ? 1 : 0;
        }
        __syncthreads();
    }
}

// ---------------------------------------------------------------------------
// K3: one warp per (b,m) column, whole column register-resident.
// dyn_k from top-10 IoUs, then dyn_k lowest-cost anchors -> g_selmask.
// All tie-breaks lowest-index (matches jax.lax.top_k stability).
// ---------------------------------------------------------------------------
__global__ void __launch_bounds__(32)
k_match() {
    int bm = blockIdx.x;  // b*M + m
    int b = bm / Mc;
    int m = bm % Mc;
    int lane = threadIdx.x;

    float cv[16], iv[16];
    #pragma unroll
    for (int r = 0; r < 16; r++) {
        int i = lane + 32 * r;
        if (i < Nc) {
            cv[r] = g_cost[(b * Nc + i) * Mc + m];
            iv[r] = g_ious[(b * Nc + i) * Mc + m];
        } else {
            cv[r] = FLT_MAX;
            iv[r] = -FLT_MAX;
        }
    }

    // dyn_k = clamp(trunc(sum of top-10 ious), 1, 10)
    float ksum = 0.0f;
    for (int k = 0; k < CANDK; k++) {
        float best = -FLT_MAX; int bi = INT_MAX;
        #pragma unroll
        for (int r = 0; r < 16; r++)
            if (iv[r] > best) { best = iv[r]; bi = lane + 32 * r; }
        #pragma unroll
        for (int o = 16; o; o >>= 1) {
            float ov = __shfl_xor_sync(0xffffffffu, best, o);
            int oi = __shfl_xor_sync(0xffffffffu, bi, o);
            if (ov > best || (ov == best && oi < bi)) { best = ov; bi = oi; }
        }
        ksum += best;
        int rr = bi >> 5, ll = bi & 31;
        #pragma unroll
        for (int r = 0; r < 16; r++)
            if (r == rr && ll == lane) iv[r] = -FLT_MAX;
    }
    int dyn = (int)ksum;
    if (dyn < 1) dyn = 1;
    if (dyn > CANDK) dyn = CANDK;

    // dyn lowest-cost anchors -> bit m of g_selmask
    for (int k = 0; k < CANDK; k++) {
        float best = FLT_MAX; int bi = INT_MAX;
        #pragma unroll
        for (int r = 0; r < 16; r++)
            if (cv[r] < best) { best = cv[r]; bi = lane + 32 * r; }
        #pragma unroll
        for (int o = 16; o; o >>= 1) {
            float ov = __shfl_xor_sync(0xffffffffu, best, o);
            int oi = __shfl_xor_sync(0xffffffffu, bi, o);
            if (ov < best || (ov == best && oi < bi)) { best = ov; bi = oi; }
        }
        if (lane == 0 && k < dyn) atomicOr(&g_selmask[b * Nc + bi], 1u << m);
        int rr = bi >> 5, ll = bi & 31;
        #pragma unroll
        for (int r = 0; r < 16; r++)
            if (r == rr && ll == lane) cv[r] = FLT_MAX;
    }
}

// ---------------------------------------------------------------------------
// K4: warp per (b,n), 1024-thread blocks (32 warps) to cut atomic contention.
// Membership = one int + popc. Last block writes the output.
// ---------------------------------------------------------------------------
__global__ void __launch_bounds__(1024)
k_loss(const float* __restrict__ logits, const float* __restrict__ boxes,
       const int* __restrict__ gtc, const float* __restrict__ gtb,
       const float* __restrict__ img, float* __restrict__ out) {
    __shared__ double sacc[5];
    int tid = threadIdx.x;
    if (tid < 5) sacc[tid] = 0.0;
    __syncthreads();

    int wid = tid >> 5;
    int lane = tid & 31;
    int g = blockIdx.x * 32 + wid;  // b*N + n

    if (g < Bc * Nc) {
        int b = g / Nc;
        int n = g % Nc;

        unsigned sel = g_selmask[g];
        int valid = g_valid[g];
        int cnt = __popc(sel);
        if (cnt > 0 && valid) {
            int matched;
            if (cnt > 1) {
                float v = (lane < Mc) ? g_cost[g * Mc + lane] : FLT_MAX;
                int bi = (lane < Mc) ? lane : INT_MAX;
                #pragma unroll
                for (int o = 16; o; o >>= 1) {
                    float ov = __shfl_xor_sync(0xffffffffu, v, o);
                    int oi = __shfl_xor_sync(0xffffffffu, bi, o);
                    if (ov < v || (ov == v && oi < bi)) { v = ov; bi = oi; }
                }
                matched = bi;
            } else {
                matched = __ffs(sel) - 1;
            }

            int gm_i = b * Mc + matched;
            int tcls = gtc[gm_i];
            float fsum = 0.0f;
            #pragma unroll
            for (int k = 0; k < 3; k++) {
                int c = lane + 32 * k;
                if (c < Cc) {
                    float l = logits[(size_t)g * Cc + c];
                    float tgt = (c == tcls) ? 1.0f : 0.0f;
                    float p = fsigm(l);
                    float ce = fmaxf(l, 0.0f) - l * tgt + log1pf(__expf(-fabsf(l)));
                    float pt = p * tgt + (1.0f - p) * (1.0f - tgt);
                    float om = 1.0f - pt;
                    float w = 0.25f * tgt + 0.75f * (1.0f - tgt);
                    fsum += ce * om * om * w;
                }
            }
            #pragma unroll
            for (int o = 16; o; o >>= 1)
                fsum += __shfl_xor_sync(0xffffffffu, fsum, o);

            if (lane == 0) {
                float i0 = img[b * 4 + 0], i1 = img[b * 4 + 1];
                float i2 = img[b * 4 + 2], i3 = img[b * 4 + 3];
                float4 bb = ((const float4*)boxes)[g];
                float nx1 = bb.x / i0, ny1 = bb.y / i1;
                float nx2 = bb.z / i2, ny2 = bb.w / i3;
                float4 gbv = ((const float4*)gtb)[gm_i];
                float mx1 = gbv.x / i0, my1 = gbv.y / i1;
                float mx2 = gbv.z / i2, my2 = gbv.w / i3;

                float l1v = fabsf(nx1 - mx1) + fabsf(ny1 - my1) +
                            fabsf(nx2 - mx2) + fabsf(ny2 - my2);

                float ltx = fmaxf(nx1, mx1), lty = fmaxf(ny1, my1);
                float rbx = fminf(nx2, mx2), rby = fminf(ny2, my2);
                float iw = fmaxf(rbx - ltx, 0.f), ih = fmaxf(rby - lty, 0.f);
                float inter = iw * ih;
                float a1 = (nx2 - nx1) * (ny2 - ny1);
                float a2 = (mx2 - mx1) * (my2 - my1);
                float uni = a1 + a2 - inter;
                float iou = inter / (uni + EPSc);
                float ex = fmaxf(fmaxf(nx2, mx2) - fminf(nx1, mx1), 0.f);
                float ey = fmaxf(fmaxf(ny2, my2) - fminf(ny1, my1), 0.f);
                float enc = ex * ey;
                float giou = iou - (enc - uni) / (enc + EPSc);
                float gv = 1.0f - giou;

                float mi = g_inter[g * Mc + matched];
                float msv = g_msum[g * Mc + matched];
                float mu = msv + g_gmsum[gm_i] + EPSc;
                float mkv = 1.0f - 2.0f * mi / mu;

                atomicAdd(&sacc[0], (double)fsum);
                atomicAdd(&sacc[1], (double)l1v);
                atomicAdd(&sacc[2], (double)gv);
                atomicAdd(&sacc[3], (double)mkv);
                atomicAdd(&sacc[4], 1.0);
            }
        }
    }
    __syncthreads();
    if (tid < 5) atomicAdd(&g_acc[tid], sacc[tid]);
    __syncthreads();
    if (tid == 0) {
        __threadfence();
        unsigned ticket = atomicAdd(&g_done, 1u);
        if (ticket == gridDim.x - 1) {
            __threadfence();
            double nt = g_acc[4];
            out[0] = (float)(2.0 * g_acc[0] / nt);
            out[1] = (float)(5.0 * g_acc[1] / nt);
            out[2] = (float)(2.0 * g_acc[2] / nt);
            out[3] = (float)(5.0 * g_acc[3] / nt);
        }
    }
}

extern "C" void kernel_launch(void* const* d_in, const int* in_sizes, int n_in,
                              void* d_out, int out_size) {
    const float* pred_logits = (const float*)d_in[0];
    const float* pred_boxes  = (const float*)d_in[1];
    const float* pred_masks  = (const float*)d_in[2];
    const int*   gt_classes  = (const int*)d_in[3];
    const float* gt_boxes    = (const float*)d_in[4];
    const float* gt_masks    = (const float*)d_in[5];
    const float* image_size  = (const float*)d_in[6];
    float* out = (float*)d_out;

    k_crop<<<Bc * Mc, 800>>>(gt_boxes, gt_masks);
    k_cost<<<COSTGRID, 512>>>(pred_logits, pred_boxes, pred_masks,
                              gt_classes, gt_boxes, image_size);
    k_match<<<Bc * Mc, 32>>>();
    k_loss<<<(Bc * Nc + 31) / 32, 1024>>>(pred_logits, pred_boxes, gt_classes,
                                          gt_boxes, image_size, out);
}